// round 11
// baseline (speedup 1.0000x reference)
#include <cuda_runtime.h>

#define T_TOTAL    262144
#define NF         64
#define TILE_ROWS  128
#define HALO       90
#define SROWS      (TILE_ROWS + HALO)      // 218
#define SMEM_F4    (SROWS * NF / 4)        // 3488
#define SMEM_BYTES (SROWS * NF * 4)        // 55808
#define THREADS    512
#define GROUPS     8
#define GROUP_ROWS (TILE_ROWS / GROUPS)    // 16

__global__ void __launch_bounds__(THREADS, 3)
ma_kernel(const float* __restrict__ x, float* __restrict__ out) {
    extern __shared__ float4 sm4[];
    float* sm = (float*)sm4;                    // [SROWS][NF]

    const int t    = threadIdx.x;
    const int blk  = blockIdx.x;
    const int base = blk * TILE_ROWS - HALO;    // global row of smem row 0

    // ---- Phase 1: stream tile + halo into smem (float4, coalesced) ----
    const float4* x4 = (const float4*)x;        // row stride NF/4 = 16
    #pragma unroll 4
    for (int idx = t; idx < SMEM_F4; idx += THREADS) {
        int gr = base + (idx >> 4);
        float4 v;
        if (gr >= 0) {
            v = __ldcg(&x4[idx + base * (NF / 4)]);
        } else {
            v = make_float4(0.f, 0.f, 0.f, 0.f);   // zero-pad rows < 0
        }
        sm4[idx] = v;
    }
    __syncthreads();

    // ---- Phase 2: one column per thread, 16-row strip per group ----
    const int c   = t & (NF - 1);               // column 0..63 (lane-contiguous)
    const int g   = t >> 6;                     // group 0..7
    const int lr0 = HALO + g * GROUP_ROWS;      // first smem row of strip
    const int gr0 = blk * TILE_ROWS + g * GROUP_ROWS;

    float s7 = 0.f, s30 = 0.f, s90 = 0.f;

    // Entry sums over the 90 rows preceding the strip (zero-padded for blk 0).
    #pragma unroll 10
    for (int k = 1; k <= HALO; k++) {
        float v = sm[(lr0 - k) * NF + c];
        s90 += v;
        if (k <= 30) s30 += v;
        if (k <= 7)  s7  += v;
    }

    const float inv7  = 1.0f / 7.0f;
    const float inv30 = 1.0f / 30.0f;
    const float inv90 = 1.0f / 90.0f;

    float* oc = out + c;                        // out row stride 4*NF

    if (gr0 < 90) {
        // Careful region (blk 0, groups 0..5 only): expanding divisors;
        // zero-padded halo makes sliding sums equal the cumsum automatically.
        #pragma unroll
        for (int j = 0; j < GROUP_ROWS; j++) {
            int lr = lr0 + j;
            int gi = gr0 + j;
            float v   = sm[lr * NF + c];
            float v7  = sm[(lr - 7)  * NF + c];
            float v30 = sm[(lr - 30) * NF + c];
            float v90 = sm[(lr - 90) * NF + c];
            s7 += v - v7; s30 += v - v30; s90 += v - v90;
            float rn  = 1.0f / (float)(gi + 1);
            float r7  = (gi >= 6)  ? inv7  : rn;
            float r30 = (gi >= 29) ? inv30 : rn;
            float r90 = (gi >= 89) ? inv90 : rn;
            float* o = oc + gi * (4 * NF);
            __stcs(o,          v);
            __stcs(o + NF,     s7  * r7);
            __stcs(o + 2 * NF, s30 * r30);
            __stcs(o + 3 * NF, s90 * r90);
        }
    } else {
        #pragma unroll
        for (int j = 0; j < GROUP_ROWS; j++) {
            int lr = lr0 + j;
            int gi = gr0 + j;
            float v   = sm[lr * NF + c];
            float v7  = sm[(lr - 7)  * NF + c];
            float v30 = sm[(lr - 30) * NF + c];
            float v90 = sm[(lr - 90) * NF + c];
            s7 += v - v7; s30 += v - v30; s90 += v - v90;
            float* o = oc + gi * (4 * NF);
            __stcs(o,          v);
            __stcs(o + NF,     s7  * inv7);
            __stcs(o + 2 * NF, s30 * inv30);
            __stcs(o + 3 * NF, s90 * inv90);
        }
    }
}

extern "C" void kernel_launch(void* const* d_in, const int* in_sizes, int n_in,
                              void* d_out, int out_size) {
    const float* x  = (const float*)d_in[0];
    float*      out = (float*)d_out;
    static int attr_set = 0;
    if (!attr_set) {
        cudaFuncSetAttribute(ma_kernel,
                             cudaFuncAttributeMaxDynamicSharedMemorySize,
                             SMEM_BYTES);
        attr_set = 1;
    }
    int n_blocks = T_TOTAL / TILE_ROWS;         // 2048
    ma_kernel<<<n_blocks, THREADS, SMEM_BYTES>>>(x, out);
}

// round 12
// speedup vs baseline: 1.6473x; 1.6473x over previous
#include <cuda_runtime.h>
#include <cstdint>

#define T_TOTAL    262144
#define NF         64
#define XR4        (NF / 4)            // 16 float4 per x row
#define TILE_ROWS  256
#define HALO       90
#define SROWS      (TILE_ROWS + HALO)  // 346
#define SMEM_F4    (SROWS * XR4)       // 5536
#define SMEM_BYTES (SMEM_F4 * 16)      // 88576
#define THREADS    512
#define GROUPS     8
#define GROUP_ROWS (TILE_ROWS / GROUPS)  // 32

__global__ void __launch_bounds__(THREADS, 2)
ma_kernel(const float* __restrict__ x, float* __restrict__ out) {
    extern __shared__ float4 sm4[];
    float* sm = (float*)sm4;                    // [SROWS][NF]

    const int t    = threadIdx.x;
    const int blk  = blockIdx.x;
    const int base = blk * TILE_ROWS - HALO;    // global row of smem row 0

    // ---- Phase 1: cp.async stream tile + halo into smem ----
    const int pad = (blk == 0) ? HALO : 0;      // rows < 0 are implicit zeros
    if (pad) {
        for (int idx = t; idx < pad * XR4; idx += THREADS)
            sm4[idx] = make_float4(0.f, 0.f, 0.f, 0.f);
    }
    {
        uint32_t sdst = (uint32_t)__cvta_generic_to_shared(sm4 + pad * XR4);
        const float4* src = (const float4*)x + (base + pad) * XR4;
        const int n4 = (SROWS - pad) * XR4;
        #pragma unroll 4
        for (int idx = t; idx < n4; idx += THREADS) {
            asm volatile("cp.async.cg.shared.global [%0], [%1], 16;" ::
                         "r"(sdst + (uint32_t)idx * 16u), "l"(src + idx));
        }
        asm volatile("cp.async.commit_group;");
        asm volatile("cp.async.wait_group 0;");
    }
    __syncthreads();

    // ---- Phase 2: one column per thread, 32-row strip per group ----
    const int c   = t & (NF - 1);               // column 0..63 (lane-contiguous)
    const int g   = t >> 6;                     // group 0..7
    const int lr0 = HALO + g * GROUP_ROWS;      // first smem row of strip
    const int gr0 = blk * TILE_ROWS + g * GROUP_ROWS;

    float s7 = 0.f, s30 = 0.f, s90 = 0.f;

    // Entry sums over the 90 rows preceding the strip (zero-padded for blk 0).
    #pragma unroll 10
    for (int k = 1; k <= HALO; k++) {
        float v = sm[(lr0 - k) * NF + c];
        s90 += v;
        if (k <= 30) s30 += v;
        if (k <= 7)  s7  += v;
    }

    const float inv7  = 1.0f / 7.0f;
    const float inv30 = 1.0f / 30.0f;
    const float inv90 = 1.0f / 90.0f;

    float* oc = out + c;                        // out row stride 4*NF
    float hist[GROUP_ROWS];

    if (gr0 < 90) {
        // Careful region (blk 0, groups 0..2): expanding divisors; zero-padded
        // halo makes the sliding sums equal the cumsum automatically.
        #pragma unroll
        for (int j = 0; j < GROUP_ROWS; j++) {
            int lr = lr0 + j;
            int gi = gr0 + j;
            float v   = sm[lr * NF + c];
            hist[j] = v;
            float v7  = (j >= 7)  ? hist[j - 7]  : sm[(lr - 7)  * NF + c];
            float v30 = (j >= 30) ? hist[j - 30] : sm[(lr - 30) * NF + c];
            float v90 = sm[(lr - 90) * NF + c];
            s7 += v - v7; s30 += v - v30; s90 += v - v90;
            float rn  = 1.0f / (float)(gi + 1);
            float r7  = (gi >= 6)  ? inv7  : rn;
            float r30 = (gi >= 29) ? inv30 : rn;
            float r90 = (gi >= 89) ? inv90 : rn;
            float* o = oc + gi * (4 * NF);
            __stcs(o,          v);
            __stcs(o + NF,     s7  * r7);
            __stcs(o + 2 * NF, s30 * r30);
            __stcs(o + 3 * NF, s90 * r90);
        }
    } else {
        #pragma unroll
        for (int j = 0; j < GROUP_ROWS; j++) {
            int lr = lr0 + j;
            int gi = gr0 + j;
            float v   = sm[lr * NF + c];
            hist[j] = v;
            float v7  = (j >= 7)  ? hist[j - 7]  : sm[(lr - 7)  * NF + c];
            float v30 = (j >= 30) ? hist[j - 30] : sm[(lr - 30) * NF + c];
            float v90 = sm[(lr - 90) * NF + c];
            s7 += v - v7; s30 += v - v30; s90 += v - v90;
            float* o = oc + gi * (4 * NF);
            __stcs(o,          v);
            __stcs(o + NF,     s7  * inv7);
            __stcs(o + 2 * NF, s30 * inv30);
            __stcs(o + 3 * NF, s90 * inv90);
        }
    }
}

extern "C" void kernel_launch(void* const* d_in, const int* in_sizes, int n_in,
                              void* d_out, int out_size) {
    const float* x  = (const float*)d_in[0];
    float*      out = (float*)d_out;
    static int attr_set = 0;
    if (!attr_set) {
        cudaFuncSetAttribute(ma_kernel,
                             cudaFuncAttributeMaxDynamicSharedMemorySize,
                             SMEM_BYTES);
        attr_set = 1;
    }
    int n_blocks = T_TOTAL / TILE_ROWS;         // 1024
    ma_kernel<<<n_blocks, THREADS, SMEM_BYTES>>>(x, out);
}